// round 1
// baseline (speedup 1.0000x reference)
#include <cuda_runtime.h>
#include <cuda_bf16.h>
#include <cstdint>

#define B_ 16
#define D_ 128
#define M_ 2048
#define N_ 4096

// Normalized rows, bf16, layout [b][n][d] row-major (256B rows). 16.8 MB scratch.
__device__ __nv_bfloat16 g_zn[(size_t)B_ * N_ * D_];

// ---------------------------------------------------------------- zero output
__global__ void zero_out_kernel(float* out, int n) {
    int i = blockIdx.x * blockDim.x + threadIdx.x;
    if (i < n) out[i] = 0.f;
}

// ------------------------------------------------------- normalize + transpose
// Input Z[b][d][m] fp32 -> g_zn[b][src*M+m][d] bf16 with 1/max(||z||,1e-8).
__global__ void normalize_kernel(const float* __restrict__ Zi,
                                 const float* __restrict__ Zj) {
    __shared__ float tile[D_][33];
    __shared__ float part[8][32];
    __shared__ float rnorm_s[32];
    const int m0  = blockIdx.x * 32;
    const int src = blockIdx.y;
    const int b   = blockIdx.z;
    const float* Z = src ? Zj : Zi;
    const int tid = threadIdx.x;
    const int tx = tid & 31;   // m
    const int ty = tid >> 5;   // 0..7

    const float* base = Z + (size_t)b * D_ * M_ + m0 + tx;
    float ss = 0.f;
#pragma unroll
    for (int d = ty; d < D_; d += 8) {
        float v = base[(size_t)d * M_];
        tile[d][tx] = v;
        ss += v * v;
    }
    part[ty][tx] = ss;
    __syncthreads();
    if (ty == 0) {
        float s = 0.f;
#pragma unroll
        for (int k = 0; k < 8; k++) s += part[k][tx];
        rnorm_s[tx] = 1.f / fmaxf(sqrtf(s), 1e-8f);
    }
    __syncthreads();

    unsigned* out32 = reinterpret_cast<unsigned*>(g_zn);
    const size_t nbase = (size_t)b * N_ + (size_t)src * M_ + m0;
#pragma unroll
    for (int it = 0; it < 8; it++) {
        int idx = it * 256 + tid;      // 0..2047
        int r  = idx >> 6;             // row within 32-row tile
        int dp = idx & 63;             // d-pair
        float rn = rnorm_s[r];
        float v0 = tile[2 * dp][r] * rn;
        float v1 = tile[2 * dp + 1][r] * rn;
        __nv_bfloat162 h2 = __floats2bfloat162_rn(v0, v1);
        out32[(nbase + r) * (D_ / 2) + dp] = *reinterpret_cast<unsigned*>(&h2);
    }
}

// ------------------------------------------------------------------- helpers
__device__ __forceinline__ unsigned swz_off(int row, int ch) {
    // 256B rows, 16 chunks of 16B, XOR-8 swizzle -> conflict-free ldmatrix
    return (unsigned)(row * 256 + ((ch ^ (row & 7)) << 4));
}

__device__ __forceinline__ void ldsm_x4(unsigned addr, unsigned& r0, unsigned& r1,
                                        unsigned& r2, unsigned& r3) {
    asm volatile("ldmatrix.sync.aligned.m8n8.x4.shared.b16 {%0,%1,%2,%3}, [%4];"
                 : "=r"(r0), "=r"(r1), "=r"(r2), "=r"(r3) : "r"(addr));
}

__device__ __forceinline__ void mma_bf16(float* c, const unsigned* a,
                                         unsigned b0, unsigned b1) {
    asm volatile("mma.sync.aligned.m16n8k16.row.col.f32.bf16.bf16.f32 "
                 "{%0,%1,%2,%3}, {%4,%5,%6,%7}, {%8,%9}, {%0,%1,%2,%3};"
                 : "+f"(c[0]), "+f"(c[1]), "+f"(c[2]), "+f"(c[3])
                 : "r"(a[0]), "r"(a[1]), "r"(a[2]), "r"(a[3]), "r"(b0), "r"(b1));
}

__device__ __forceinline__ float ex2f(float x) {
    float y; asm("ex2.approx.f32 %0, %1;" : "=f"(y) : "f"(x)); return y;
}
__device__ __forceinline__ float lg2f(float x) {
    float y; asm("lg2.approx.f32 %0, %1;" : "=f"(y) : "f"(x)); return y;
}

__device__ __forceinline__ void cp16(unsigned dst, const void* src) {
    asm volatile("cp.async.cg.shared.global [%0], [%1], 16;"
                 :: "r"(dst), "l"(src) : "memory");
}

// ------------------------------------------------------------------ main pass
// grid (N/128, B), 256 threads (8 warps: 4 row-groups x 2 col-groups).
// SMEM: A tile 32KB (resident) + B double buffer 64KB + rowsum/rowpos.
__global__ __launch_bounds__(256, 1) void simclr_main_kernel(float* __restrict__ out) {
    extern __shared__ char smem[];
    const int b   = blockIdx.y;
    const int i0  = blockIdx.x * 128;
    const int tid = threadIdx.x;
    const int lane = tid & 31, w = tid >> 5;
    const int wr = w >> 1;              // 0..3 -> 32-row band
    const int wc = w & 1;               // 0..1 -> 64-col band

    float* rowsum = (float*)(smem + 98304);
    float* rowpos = rowsum + 128;
    unsigned sA = (unsigned)__cvta_generic_to_shared(smem);
    unsigned sBb[2] = { (unsigned)__cvta_generic_to_shared(smem + 32768),
                        (unsigned)__cvta_generic_to_shared(smem + 65536) };

    if (tid < 128) { rowsum[tid] = 0.f; rowpos[tid] = 0.f; }

    const char* zb = (const char*)(g_zn + (size_t)b * N_ * D_);

    // prologue: A tile + B tile 0
    {
        const char* Ag = zb + (size_t)i0 * 256;
#pragma unroll
        for (int it = 0; it < 8; it++) {
            int idx = it * 256 + tid;
            int row = idx >> 4, ch = idx & 15;
            cp16(sA + swz_off(row, ch), Ag + row * 256 + ch * 16);
        }
#pragma unroll
        for (int it = 0; it < 8; it++) {
            int idx = it * 256 + tid;
            int row = idx >> 4, ch = idx & 15;
            cp16(sBb[0] + swz_off(row, ch), zb + row * 256 + ch * 16);
        }
        asm volatile("cp.async.commit_group;" ::: "memory");
    }

    float sum_l[4] = {0.f, 0.f, 0.f, 0.f};   // index = mi*2 + rowhalf
    float pos_l[4] = {0.f, 0.f, 0.f, 0.f};
    const int rowA = wr * 32;
    const int colB = wc * 64;
    const float SC = 2.8853900817779268f;    // 2*log2(e); logits = 2*dot, shift 2

    for (int jt = 0; jt < 32; jt++) {
        if (jt + 1 < 32) {
            const char* Bg = zb + (size_t)(jt + 1) * 128 * 256;
#pragma unroll
            for (int it = 0; it < 8; it++) {
                int idx = it * 256 + tid;
                int row = idx >> 4, ch = idx & 15;
                cp16(sBb[(jt + 1) & 1] + swz_off(row, ch), Bg + row * 256 + ch * 16);
            }
            asm volatile("cp.async.commit_group;" ::: "memory");
            asm volatile("cp.async.wait_group 1;" ::: "memory");
        } else {
            asm volatile("cp.async.wait_group 0;" ::: "memory");
        }
        __syncthreads();

        const unsigned sBt = sBb[jt & 1];
        float acc[2][8][4];
#pragma unroll
        for (int mi = 0; mi < 2; mi++)
#pragma unroll
            for (int ng = 0; ng < 8; ng++)
#pragma unroll
                for (int q = 0; q < 4; q++) acc[mi][ng][q] = 0.f;

#pragma unroll
        for (int k = 0; k < 8; k++) {
            unsigned a[2][4], bb[4][4];
            const int ch = 2 * k + (lane >> 4);
            const int rl = lane & 15;
#pragma unroll
            for (int mi = 0; mi < 2; mi++)
                ldsm_x4(sA + swz_off(rowA + mi * 16 + rl, ch),
                        a[mi][0], a[mi][1], a[mi][2], a[mi][3]);
#pragma unroll
            for (int g = 0; g < 4; g++)
                ldsm_x4(sBt + swz_off(colB + g * 16 + rl, ch),
                        bb[g][0], bb[g][1], bb[g][2], bb[g][3]);
#pragma unroll
            for (int mi = 0; mi < 2; mi++)
#pragma unroll
                for (int ng = 0; ng < 8; ng++)
                    mma_bf16(acc[mi][ng], a[mi],
                             bb[ng >> 1][ng & 1], bb[ng >> 1][(ng & 1) + 2]);
        }

        const int j0 = jt * 128;
        const bool diagT = (j0 == i0);
        const bool posT  = (j0 == ((i0 + M_) & (N_ - 1)));
        if (!diagT && !posT) {
            // fast path: FFMA + EX2 + FADD only
#pragma unroll
            for (int mi = 0; mi < 2; mi++)
#pragma unroll
                for (int ng = 0; ng < 8; ng++)
#pragma unroll
                    for (int q = 0; q < 4; q++)
                        sum_l[mi * 2 + (q >> 1)] += ex2f(acc[mi][ng][q] * SC - SC);
        } else {
#pragma unroll
            for (int mi = 0; mi < 2; mi++)
#pragma unroll
                for (int q = 0; q < 4; q++) {
                    const int gr = i0 + rowA + mi * 16 + (q >> 1) * 8 + (lane >> 2);
#pragma unroll
                    for (int ng = 0; ng < 8; ng++) {
                        const int gc = j0 + colB + ng * 8 + ((lane & 3) << 1) + (q & 1);
                        const float d = acc[mi][ng][q];
                        if (!(diagT && gc == gr))
                            sum_l[mi * 2 + (q >> 1)] += ex2f(d * SC - SC);
                        if (posT && gc == ((gr + M_) & (N_ - 1)))
                            pos_l[mi * 2 + (q >> 1)] += 2.f * d;
                    }
                }
        }
        __syncthreads();
    }

    // reduce across the 4 lanes of each quad (they share rows)
#pragma unroll
    for (int i = 0; i < 4; i++) {
        sum_l[i] += __shfl_xor_sync(0xffffffffu, sum_l[i], 1);
        sum_l[i] += __shfl_xor_sync(0xffffffffu, sum_l[i], 2);
        pos_l[i] += __shfl_xor_sync(0xffffffffu, pos_l[i], 1);
        pos_l[i] += __shfl_xor_sync(0xffffffffu, pos_l[i], 2);
    }
    if ((lane & 3) == 0) {
#pragma unroll
        for (int i = 0; i < 4; i++) {
            int rloc = rowA + (i >> 1) * 16 + (i & 1) * 8 + (lane >> 2);
            atomicAdd(&rowsum[rloc], sum_l[i]);
            atomicAdd(&rowpos[rloc], pos_l[i]);
        }
    }
    __syncthreads();

    __shared__ float lred[128];
    if (tid < 128) {
        float lse = 2.f + lg2f(rowsum[tid]) * 0.6931471805599453f;
        lred[tid] = lse - rowpos[tid];
    }
    __syncthreads();
    if (tid == 0) {
        float s = 0.f;
        for (int i = 0; i < 128; i++) s += lred[i];
        atomicAdd(out, s * (1.f / ((float)B_ * (float)N_)));
    }
}

// ----------------------------------------------------------------- entry point
extern "C" void kernel_launch(void* const* d_in, const int* in_sizes, int n_in,
                              void* d_out, int out_size) {
    const float* Zi = (const float*)d_in[0];
    const float* Zj = (const float*)d_in[1];
    float* out = (float*)d_out;
    (void)in_sizes; (void)n_in;

    cudaFuncSetAttribute(simclr_main_kernel,
                         cudaFuncAttributeMaxDynamicSharedMemorySize, 99328);

    zero_out_kernel<<<(out_size + 255) / 256, 256>>>(out, out_size);
    normalize_kernel<<<dim3(M_ / 32, 2, B_), 256>>>(Zi, Zj);
    simclr_main_kernel<<<dim3(N_ / 128, B_), 256, 99328>>>(out);
}

// round 3
// speedup vs baseline: 1.5389x; 1.5389x over previous
#include <cuda_runtime.h>
#include <cuda_bf16.h>
#include <cstdint>

#define B_ 16
#define D_ 128
#define M_ 2048
#define N_ 4096
#define NT 32                 // 128-row tiles per batch
#define NPAIR (NT * (NT + 1) / 2)   // 528

// Normalized rows, bf16, [b][n][d] row-major (256B rows)
__device__ __align__(16) __nv_bfloat16 g_zn[(size_t)B_ * N_ * D_];
// Per-row sum(exp) and positive-logit accumulators
__device__ float g_rowsum[B_ * N_];
__device__ float g_rowpos[B_ * N_];

// ---------------------------------------------------------------- zero scratch
__global__ void zero_kernel(float* out, int n_out) {
    int i = blockIdx.x * blockDim.x + threadIdx.x;
    if (i < B_ * N_) { g_rowsum[i] = 0.f; g_rowpos[i] = 0.f; }
    if (i < n_out) out[i] = 0.f;
}

// ------------------------------------------------------- normalize + transpose
__global__ void normalize_kernel(const float* __restrict__ Zi,
                                 const float* __restrict__ Zj) {
    __shared__ float tile[D_][33];
    __shared__ float part[8][32];
    __shared__ float rnorm_s[32];
    const int m0  = blockIdx.x * 32;
    const int src = blockIdx.y;
    const int b   = blockIdx.z;
    const float* Z = src ? Zj : Zi;
    const int tid = threadIdx.x;
    const int tx = tid & 31, ty = tid >> 5;

    const float* base = Z + (size_t)b * D_ * M_ + m0 + tx;
    float ss = 0.f;
#pragma unroll
    for (int d = ty; d < D_; d += 8) {
        float v = base[(size_t)d * M_];
        tile[d][tx] = v;
        ss += v * v;
    }
    part[ty][tx] = ss;
    __syncthreads();
    if (ty == 0) {
        float s = 0.f;
#pragma unroll
        for (int k = 0; k < 8; k++) s += part[k][tx];
        rnorm_s[tx] = 1.f / fmaxf(sqrtf(s), 1e-8f);
    }
    __syncthreads();

    unsigned* out32 = reinterpret_cast<unsigned*>(g_zn);
    const size_t nbase = (size_t)b * N_ + (size_t)src * M_ + m0;
#pragma unroll
    for (int it = 0; it < 8; it++) {
        int idx = it * 256 + tid;
        int r  = idx >> 6;
        int dp = idx & 63;
        float rn = rnorm_s[r];
        float v0 = tile[2 * dp][r] * rn;
        float v1 = tile[2 * dp + 1][r] * rn;
        __nv_bfloat162 h2 = __floats2bfloat162_rn(v0, v1);
        out32[(nbase + r) * (D_ / 2) + dp] = *reinterpret_cast<unsigned*>(&h2);
    }
}

// ------------------------------------------------------------------- helpers
__device__ __forceinline__ unsigned swz_off(int row, int ch) {
    return (unsigned)(row * 256 + ((ch ^ (row & 7)) << 4));
}
__device__ __forceinline__ void ldsm_x4(unsigned addr, unsigned& r0, unsigned& r1,
                                        unsigned& r2, unsigned& r3) {
    asm volatile("ldmatrix.sync.aligned.m8n8.x4.shared.b16 {%0,%1,%2,%3}, [%4];"
                 : "=r"(r0), "=r"(r1), "=r"(r2), "=r"(r3) : "r"(addr));
}
__device__ __forceinline__ void mma_bf16(float* c, const unsigned* a,
                                         unsigned b0, unsigned b1) {
    asm volatile("mma.sync.aligned.m16n8k16.row.col.f32.bf16.bf16.f32 "
                 "{%0,%1,%2,%3}, {%4,%5,%6,%7}, {%8,%9}, {%0,%1,%2,%3};"
                 : "+f"(c[0]), "+f"(c[1]), "+f"(c[2]), "+f"(c[3])
                 : "r"(a[0]), "r"(a[1]), "r"(a[2]), "r"(a[3]), "r"(b0), "r"(b1));
}
__device__ __forceinline__ float ex2f(float x) {
    float y; asm("ex2.approx.f32 %0, %1;" : "=f"(y) : "f"(x)); return y;
}
__device__ __forceinline__ float lg2f(float x) {
    float y; asm("lg2.approx.f32 %0, %1;" : "=f"(y) : "f"(x)); return y;
}
__device__ __forceinline__ void cp16(unsigned dst, const void* src) {
    asm volatile("cp.async.cg.shared.global [%0], [%1], 16;"
                 :: "r"(dst), "l"(src) : "memory");
}

// ------------------------------------------------------------------ main pass
// One CTA per upper-triangle tile pair (i <= j). 256 threads = 8 warps,
// 4 row-bands x 2 col-bands. Symmetry: tile (i,j) feeds rowsum of tile-i rows
// (row sums) AND tile-j rows (column sums).
__global__ __launch_bounds__(256, 2) void simclr_pair_kernel() {
    extern __shared__ char smem[];
    __shared__ float asum[128], bsum[128], apos[128], bpos[128];

    const int p = blockIdx.x;
    const int b = blockIdx.y;
    // decode p -> (ti, tj), j >= i
    int ti = (int)(32.5f - sqrtf(32.5f * 32.5f - 2.0f * (float)p));
    while (ti > 0 && ti * 32 - ti * (ti - 1) / 2 > p) ti--;
    while ((ti + 1) * 32 - (ti + 1) * ti / 2 <= p) ti++;
    const int tj = ti + p - (ti * 32 - ti * (ti - 1) / 2);

    const int tid = threadIdx.x;
    const int lane = tid & 31, w = tid >> 5;
    const int rowA = (w >> 1) * 32;     // A-row band
    const int colB = (w & 1) * 64;      // B-col band

    unsigned sA = (unsigned)__cvta_generic_to_shared(smem);
    unsigned sB = sA + 32768;

    if (tid < 128) { asum[tid] = 0.f; apos[tid] = 0.f; }
    else { bsum[tid - 128] = 0.f; bpos[tid - 128] = 0.f; }

    // load both tiles
    const char* zb = (const char*)(g_zn + (size_t)b * N_ * D_);
    const char* Ag = zb + (size_t)ti * 128 * 256;
    const char* Bg = zb + (size_t)tj * 128 * 256;
#pragma unroll
    for (int it = 0; it < 8; it++) {
        int idx = it * 256 + tid;
        int row = idx >> 4, ch = idx & 15;
        cp16(sA + swz_off(row, ch), Ag + row * 256 + ch * 16);
        cp16(sB + swz_off(row, ch), Bg + row * 256 + ch * 16);
    }
    asm volatile("cp.async.commit_group;" ::: "memory");
    asm volatile("cp.async.wait_group 0;" ::: "memory");
    __syncthreads();

    // 128x128x128 MMA
    float acc[2][8][4];
#pragma unroll
    for (int mi = 0; mi < 2; mi++)
#pragma unroll
        for (int ng = 0; ng < 8; ng++)
#pragma unroll
            for (int q = 0; q < 4; q++) acc[mi][ng][q] = 0.f;

#pragma unroll
    for (int k = 0; k < 8; k++) {
        unsigned a[2][4], bb[4][4];
        const int ch = 2 * k + (lane >> 4);
        const int rl = lane & 15;
#pragma unroll
        for (int mi = 0; mi < 2; mi++)
            ldsm_x4(sA + swz_off(rowA + mi * 16 + rl, ch),
                    a[mi][0], a[mi][1], a[mi][2], a[mi][3]);
#pragma unroll
        for (int g = 0; g < 4; g++)
            ldsm_x4(sB + swz_off(colB + g * 16 + rl, ch),
                    bb[g][0], bb[g][1], bb[g][2], bb[g][3]);
#pragma unroll
        for (int mi = 0; mi < 2; mi++)
#pragma unroll
            for (int ng = 0; ng < 8; ng++)
                mma_bf16(acc[mi][ng], a[mi],
                         bb[ng >> 1][ng & 1], bb[ng >> 1][(ng & 1) + 2]);
    }

    // transform: acc <- exp2(acc*SC - SC); handle diag / positive pairs
    const float SC = 2.8853900817779268f;    // 2*log2(e)
    const bool dt = (ti == tj);
    const bool pt = (tj == ti + 16);
    if (!dt && !pt) {
#pragma unroll
        for (int mi = 0; mi < 2; mi++)
#pragma unroll
            for (int ng = 0; ng < 8; ng++)
#pragma unroll
                for (int q = 0; q < 4; q++)
                    acc[mi][ng][q] = ex2f(acc[mi][ng][q] * SC - SC);
    } else {
#pragma unroll
        for (int mi = 0; mi < 2; mi++)
#pragma unroll
            for (int ng = 0; ng < 8; ng++)
#pragma unroll
                for (int q = 0; q < 4; q++) {
                    const int lr = rowA + mi * 16 + (q >> 1) * 8 + (lane >> 2);
                    const int lc = colB + ng * 8 + ((lane & 3) << 1) + (q & 1);
                    const float dv = acc[mi][ng][q];
                    if (pt && lr == lc) {
                        atomicAdd(&apos[lr], 2.f * dv);
                        atomicAdd(&bpos[lr], 2.f * dv);
                    }
                    acc[mi][ng][q] = (dt && lr == lc) ? 0.f
                                   : ex2f(dv * SC - SC);
                }
    }

    // row sums (A rows): reduce over quad lanes (cols)
#pragma unroll
    for (int idx = 0; idx < 4; idx++) {
        const int mi = idx >> 1, qh = idx & 1;
        float rs = 0.f;
#pragma unroll
        for (int ng = 0; ng < 8; ng++)
            rs += acc[mi][ng][2 * qh] + acc[mi][ng][2 * qh + 1];
        rs += __shfl_xor_sync(0xffffffffu, rs, 1);
        rs += __shfl_xor_sync(0xffffffffu, rs, 2);
        if ((lane & 3) == 0)
            atomicAdd(&asum[rowA + mi * 16 + qh * 8 + (lane >> 2)], rs);
    }

    // column sums (B rows): reduce over row lanes; skip if diagonal tile
    if (!dt) {
#pragma unroll
        for (int ng = 0; ng < 8; ng++)
#pragma unroll
            for (int ql = 0; ql < 2; ql++) {
                float cs = acc[0][ng][ql] + acc[0][ng][ql + 2]
                         + acc[1][ng][ql] + acc[1][ng][ql + 2];
                cs += __shfl_xor_sync(0xffffffffu, cs, 4);
                cs += __shfl_xor_sync(0xffffffffu, cs, 8);
                cs += __shfl_xor_sync(0xffffffffu, cs, 16);
                if (lane < 4)
                    atomicAdd(&bsum[colB + ng * 8 + lane * 2 + ql], cs);
            }
    }
    __syncthreads();

    // push to global per-row accumulators
    const int base_i = b * N_ + ti * 128;
    const int base_j = b * N_ + tj * 128;
    if (tid < 128) {
        atomicAdd(&g_rowsum[base_i + tid], asum[tid]);
        if (pt) atomicAdd(&g_rowpos[base_i + tid], apos[tid]);
    } else {
        const int t = tid - 128;
        if (!dt) atomicAdd(&g_rowsum[base_j + t], bsum[t]);
        if (pt) atomicAdd(&g_rowpos[base_j + t], bpos[t]);
    }
}

// -------------------------------------------------------------------- finalize
__global__ void finalize_kernel(float* __restrict__ out) {
    const int r = blockIdx.x * 256 + threadIdx.x;     // 65536 rows
    float v = 2.f + lg2f(g_rowsum[r]) * 0.6931471805599453f - g_rowpos[r];
#pragma unroll
    for (int o = 16; o > 0; o >>= 1) v += __shfl_xor_sync(0xffffffffu, v, o);
    __shared__ float red[8];
    const int w = threadIdx.x >> 5;
    if ((threadIdx.x & 31) == 0) red[w] = v;
    __syncthreads();
    if (threadIdx.x == 0) {
        float s = 0.f;
#pragma unroll
        for (int k = 0; k < 8; k++) s += red[k];
        atomicAdd(out, s * (1.f / ((float)B_ * (float)N_)));
    }
}

// ----------------------------------------------------------------- entry point
extern "C" void kernel_launch(void* const* d_in, const int* in_sizes, int n_in,
                              void* d_out, int out_size) {
    const float* Zi = (const float*)d_in[0];
    const float* Zj = (const float*)d_in[1];
    float* out = (float*)d_out;
    (void)in_sizes; (void)n_in;

    cudaFuncSetAttribute(simclr_pair_kernel,
                         cudaFuncAttributeMaxDynamicSharedMemorySize, 65536);

    zero_kernel<<<(B_ * N_ + 255) / 256, 256>>>(out, out_size);
    normalize_kernel<<<dim3(M_ / 32, 2, B_), 256>>>(Zi, Zj);
    simclr_pair_kernel<<<dim3(NPAIR, B_), 256, 65536>>>();
    finalize_kernel<<<B_ * N_ / 256, 256>>>(out);
}

// round 4
// speedup vs baseline: 1.9271x; 1.2523x over previous
#include <cuda_runtime.h>
#include <cuda_bf16.h>
#include <cstdint>

#define B_ 16
#define D_ 128
#define M_ 2048
#define N_ 4096
#define NT 32                 // 128-row tiles per batch
#define CHUNKS 144            // sum_i ceil((32-i)/4)

// Normalized rows, bf16, [b][n][d] row-major (256B rows)
__device__ __align__(16) __nv_bfloat16 g_zn[(size_t)B_ * N_ * D_];
// Per-row sum(exp) and positive-logit accumulators
__device__ float g_rowsum[B_ * N_];
__device__ float g_rowpos[B_ * N_];

// ---------------------------------------------------------------- zero scratch
__global__ void zero_kernel(float* out, int n_out) {
    int i = blockIdx.x * blockDim.x + threadIdx.x;
    if (i < B_ * N_) { g_rowsum[i] = 0.f; g_rowpos[i] = 0.f; }
    if (i < n_out) out[i] = 0.f;
}

// ------------------------------------------------------- normalize + transpose
__global__ void normalize_kernel(const float* __restrict__ Zi,
                                 const float* __restrict__ Zj) {
    __shared__ float tile[D_][33];
    __shared__ float part[8][32];
    __shared__ float rnorm_s[32];
    const int m0  = blockIdx.x * 32;
    const int src = blockIdx.y;
    const int b   = blockIdx.z;
    const float* Z = src ? Zj : Zi;
    const int tid = threadIdx.x;
    const int tx = tid & 31, ty = tid >> 5;

    const float* base = Z + (size_t)b * D_ * M_ + m0 + tx;
    float ss = 0.f;
#pragma unroll
    for (int d = ty; d < D_; d += 8) {
        float v = base[(size_t)d * M_];
        tile[d][tx] = v;
        ss += v * v;
    }
    part[ty][tx] = ss;
    __syncthreads();
    if (ty == 0) {
        float s = 0.f;
#pragma unroll
        for (int k = 0; k < 8; k++) s += part[k][tx];
        rnorm_s[tx] = 1.f / fmaxf(sqrtf(s), 1e-8f);
    }
    __syncthreads();

    unsigned* out32 = reinterpret_cast<unsigned*>(g_zn);
    const size_t nbase = (size_t)b * N_ + (size_t)src * M_ + m0;
#pragma unroll
    for (int it = 0; it < 8; it++) {
        int idx = it * 256 + tid;
        int r  = idx >> 6;
        int dp = idx & 63;
        float rn = rnorm_s[r];
        float v0 = tile[2 * dp][r] * rn;
        float v1 = tile[2 * dp + 1][r] * rn;
        __nv_bfloat162 h2 = __floats2bfloat162_rn(v0, v1);
        out32[(nbase + r) * (D_ / 2) + dp] = *reinterpret_cast<unsigned*>(&h2);
    }
}

// ------------------------------------------------------------------- helpers
__device__ __forceinline__ unsigned swz_off(int row, int ch) {
    return (unsigned)(row * 256 + ((ch ^ (row & 7)) << 4));
}
__device__ __forceinline__ void ldsm_x4(unsigned addr, unsigned& r0, unsigned& r1,
                                        unsigned& r2, unsigned& r3) {
    asm volatile("ldmatrix.sync.aligned.m8n8.x4.shared.b16 {%0,%1,%2,%3}, [%4];"
                 : "=r"(r0), "=r"(r1), "=r"(r2), "=r"(r3) : "r"(addr));
}
__device__ __forceinline__ void mma_bf16(float* c, const unsigned* a,
                                         unsigned b0, unsigned b1) {
    asm volatile("mma.sync.aligned.m16n8k16.row.col.f32.bf16.bf16.f32 "
                 "{%0,%1,%2,%3}, {%4,%5,%6,%7}, {%8,%9}, {%0,%1,%2,%3};"
                 : "+f"(c[0]), "+f"(c[1]), "+f"(c[2]), "+f"(c[3])
                 : "r"(a[0]), "r"(a[1]), "r"(a[2]), "r"(a[3]), "r"(b0), "r"(b1));
}
__device__ __forceinline__ float ex2f(float x) {
    float y; asm("ex2.approx.f32 %0, %1;" : "=f"(y) : "f"(x)); return y;
}
__device__ __forceinline__ float lg2f(float x) {
    float y; asm("lg2.approx.f32 %0, %1;" : "=f"(y) : "f"(x)); return y;
}
__device__ __forceinline__ void cp16(unsigned dst, const void* src) {
    asm volatile("cp.async.cg.shared.global [%0], [%1], 16;"
                 :: "r"(dst), "l"(src) : "memory");
}
#define CP_COMMIT() asm volatile("cp.async.commit_group;" ::: "memory")

// ------------------------------------------------------------------ main pass
// One CTA per (row-tile i, chunk of up to 4 col-tiles j). A resident,
// B double-buffered depth-2. Symmetry: tile (i,j) feeds rows of i (row sums,
// register-accumulated) AND rows of j (column sums, pushed per tile).
__global__ __launch_bounds__(256, 2) void simclr_chunk_kernel() {
    extern __shared__ char smem[];          // A 32K | B0 32K | B1 32K
    __shared__ float csum[4][128];
    __shared__ float asum[128], apos[128];

    const int b = blockIdx.y;
    // decode blockIdx.x -> (ti, j0)
    int rem = blockIdx.x, ti = 0;
    for (;;) { int c = (NT - ti + 3) >> 2; if (rem < c) break; rem -= c; ti++; }
    const int j0 = ti + rem * 4;
    const int nt = min(4, NT - j0);

    const int tid = threadIdx.x;
    const int lane = tid & 31, w = tid >> 5;
    const int rowA = (w >> 1) * 32;
    const int colB = (w & 1) * 64;

    unsigned sA = (unsigned)__cvta_generic_to_shared(smem);
    unsigned sB[2] = {sA + 32768, sA + 65536};

    if (tid < 128) { asum[tid] = 0.f; apos[tid] = 0.f; }

    const char* zb = (const char*)(g_zn + (size_t)b * N_ * D_);
    const char* Ag = zb + (size_t)ti * 128 * 256;
    // group 0: A + B0
#pragma unroll
    for (int it = 0; it < 8; it++) {
        int idx = it * 256 + tid;
        int row = idx >> 4, ch = idx & 15;
        cp16(sA + swz_off(row, ch), Ag + row * 256 + ch * 16);
        cp16(sB[0] + swz_off(row, ch),
             zb + (size_t)j0 * 128 * 256 + row * 256 + ch * 16);
    }
    CP_COMMIT();
    // group 1: B1 (may be empty)
    if (nt > 1) {
        const char* Bg = zb + (size_t)(j0 + 1) * 128 * 256;
#pragma unroll
        for (int it = 0; it < 8; it++) {
            int idx = it * 256 + tid;
            int row = idx >> 4, ch = idx & 15;
            cp16(sB[1] + swz_off(row, ch), Bg + row * 256 + ch * 16);
        }
    }
    CP_COMMIT();

    float rs[4] = {0.f, 0.f, 0.f, 0.f};     // per-thread row partials
    const float SC = 2.8853900817779268f;   // 2*log2(e)
    float* rowsum_b = g_rowsum + b * N_;
    float* rowpos_b = g_rowpos + b * N_;

    for (int t = 0; t < nt; t++) {
        asm volatile("cp.async.wait_group 1;" ::: "memory");
        __syncthreads();

        const int j = j0 + t;
        const unsigned sBt = sB[t & 1];

        float acc[2][8][4];
#pragma unroll
        for (int mi = 0; mi < 2; mi++)
#pragma unroll
            for (int ng = 0; ng < 8; ng++)
#pragma unroll
                for (int q = 0; q < 4; q++) acc[mi][ng][q] = 0.f;

#pragma unroll
        for (int k = 0; k < 8; k++) {
            unsigned a[2][4], bb[4][4];
            const int ch = 2 * k + (lane >> 4);
            const int rl = lane & 15;
#pragma unroll
            for (int mi = 0; mi < 2; mi++)
                ldsm_x4(sA + swz_off(rowA + mi * 16 + rl, ch),
                        a[mi][0], a[mi][1], a[mi][2], a[mi][3]);
#pragma unroll
            for (int g = 0; g < 4; g++)
                ldsm_x4(sBt + swz_off(colB + g * 16 + rl, ch),
                        bb[g][0], bb[g][1], bb[g][2], bb[g][3]);
#pragma unroll
            for (int mi = 0; mi < 2; mi++)
#pragma unroll
                for (int ng = 0; ng < 8; ng++)
                    mma_bf16(acc[mi][ng], a[mi],
                             bb[ng >> 1][ng & 1], bb[ng >> 1][(ng & 1) + 2]);
        }

        const bool dt = (j == ti);
        const bool pt = (j == ti + 16);
        if (!dt && !pt) {
#pragma unroll
            for (int mi = 0; mi < 2; mi++)
#pragma unroll
                for (int ng = 0; ng < 8; ng++)
#pragma unroll
                    for (int q = 0; q < 4; q++)
                        acc[mi][ng][q] = ex2f(acc[mi][ng][q] * SC - SC);
        } else {
#pragma unroll
            for (int mi = 0; mi < 2; mi++)
#pragma unroll
                for (int ng = 0; ng < 8; ng++)
#pragma unroll
                    for (int q = 0; q < 4; q++) {
                        const int lr = rowA + mi * 16 + (q >> 1) * 8 + (lane >> 2);
                        const int lc = colB + ng * 8 + ((lane & 3) << 1) + (q & 1);
                        const float dv = acc[mi][ng][q];
                        if (pt && lr == lc) {
                            atomicAdd(&apos[lr], 2.f * dv);
                            atomicAdd(&rowpos_b[j * 128 + lr], 2.f * dv);
                        }
                        acc[mi][ng][q] = (dt && lr == lc) ? 0.f
                                       : ex2f(dv * SC - SC);
                    }
        }

        // row partials (registers, reduced at CTA end)
#pragma unroll
        for (int idx = 0; idx < 4; idx++) {
            const int mi = idx >> 1, qh = idx & 1;
            float r = 0.f;
#pragma unroll
            for (int ng = 0; ng < 8; ng++)
                r += acc[mi][ng][2 * qh] + acc[mi][ng][2 * qh + 1];
            rs[idx] += r;
        }

        // column partials -> csum (conflict-free slots)
#pragma unroll
        for (int ng = 0; ng < 8; ng++)
#pragma unroll
            for (int ql = 0; ql < 2; ql++) {
                float cs = acc[0][ng][ql] + acc[0][ng][ql + 2]
                         + acc[1][ng][ql] + acc[1][ng][ql + 2];
                cs += __shfl_xor_sync(0xffffffffu, cs, 4);
                cs += __shfl_xor_sync(0xffffffffu, cs, 8);
                cs += __shfl_xor_sync(0xffffffffu, cs, 16);
                if (lane < 4)
                    csum[w >> 1][colB + ng * 8 + lane * 2 + ql] = cs;
            }
        __syncthreads();

        // prefetch B_{t+2} into the buffer just consumed
        if (t + 2 < nt) {
            const char* Bg = zb + (size_t)(j + 2) * 128 * 256;
            unsigned dst = sB[t & 1];
#pragma unroll
            for (int it = 0; it < 8; it++) {
                int idx = it * 256 + tid;
                int row = idx >> 4, ch = idx & 15;
                cp16(dst + swz_off(row, ch), Bg + row * 256 + ch * 16);
            }
        }
        CP_COMMIT();

        // push column sums to rows of tile j (skip diagonal tile)
        if (!dt && tid < 128) {
            float cs = (csum[0][tid] + csum[1][tid])
                     + (csum[2][tid] + csum[3][tid]);
            atomicAdd(&rowsum_b[j * 128 + tid], cs);
        }
    }

    // CTA-end: quad-reduce row partials, combine, push rows of tile ti
#pragma unroll
    for (int idx = 0; idx < 4; idx++) {
        rs[idx] += __shfl_xor_sync(0xffffffffu, rs[idx], 1);
        rs[idx] += __shfl_xor_sync(0xffffffffu, rs[idx], 2);
    }
    if ((lane & 3) == 0) {
#pragma unroll
        for (int idx = 0; idx < 4; idx++)
            atomicAdd(&asum[rowA + (idx >> 1) * 16 + (idx & 1) * 8 + (lane >> 2)],
                      rs[idx]);
    }
    __syncthreads();
    const bool had_pt = (ti + 16 >= j0) && (ti + 16 < j0 + nt);
    if (tid < 128) {
        atomicAdd(&rowsum_b[ti * 128 + tid], asum[tid]);
        if (had_pt) atomicAdd(&rowpos_b[ti * 128 + tid], apos[tid]);
    }
}

// -------------------------------------------------------------------- finalize
__global__ void finalize_kernel(float* __restrict__ out) {
    const int r = blockIdx.x * 256 + threadIdx.x;
    float v = 2.f + lg2f(g_rowsum[r]) * 0.6931471805599453f - g_rowpos[r];
#pragma unroll
    for (int o = 16; o > 0; o >>= 1) v += __shfl_xor_sync(0xffffffffu, v, o);
    __shared__ float red[8];
    const int w = threadIdx.x >> 5;
    if ((threadIdx.x & 31) == 0) red[w] = v;
    __syncthreads();
    if (threadIdx.x == 0) {
        float s = 0.f;
#pragma unroll
        for (int k = 0; k < 8; k++) s += red[k];
        atomicAdd(out, s * (1.f / ((float)B_ * (float)N_)));
    }
}

// ----------------------------------------------------------------- entry point
extern "C" void kernel_launch(void* const* d_in, const int* in_sizes, int n_in,
                              void* d_out, int out_size) {
    const float* Zi = (const float*)d_in[0];
    const float* Zj = (const float*)d_in[1];
    float* out = (float*)d_out;
    (void)in_sizes; (void)n_in;

    cudaFuncSetAttribute(simclr_chunk_kernel,
                         cudaFuncAttributeMaxDynamicSharedMemorySize, 98304);

    zero_kernel<<<(B_ * N_ + 255) / 256, 256>>>(out, out_size);
    normalize_kernel<<<dim3(M_ / 32, 2, B_), 256>>>(Zi, Zj);
    simclr_chunk_kernel<<<dim3(CHUNKS, B_), 256, 98304>>>();
    finalize_kernel<<<B_ * N_ / 256, 256>>>(out);
}